// round 9
// baseline (speedup 1.0000x reference)
#include <cuda_runtime.h>
#include <cuda_fp16.h>
#include <cstdint>

// ============================================================================
// Problem constants
// ============================================================================
#define N_ROWS   65536
#define K_CL     256
#define D_DIM    512
#define TILE_M   128
#define CHUNK    64
#define NCHUNK   (D_DIM / CHUNK)   // 8
#define THREADS  256               // 8 warps: warp tile 64x64 (2M x 4N grid)

// fp16 copy of clusters + cluster squared norms (device scratch: allowed)
__device__ __half Ch_g[K_CL * D_DIM];
__device__ float  c2_g[K_CL];

// 128B-row XOR swizzle: 16B unit index ^= (row & 7).
#define SW(off) ((off) ^ (((off) >> 3) & 0x70))

// Shared memory layout (bytes): 3-stage pipeline for A and B.
#define SM_A_BASE   0            // 3 x (128x64 fp16 = 16 KB)
#define SM_A_STRIDE 16384
#define SM_B_BASE   49152        // 3 x (256x64 fp16 = 32 KB)
#define SM_B_STRIDE 32768
#define SM_X2       147456       // 128 f32
#define SM_C2       147968       // 256 f32
#define SM_SUMS     148992       // 128 x 4 f32 = 2 KB
#define SM_INV      151040       // 128 f32
#define SMEM_TOTAL  151552       // < 227 KB, 1 CTA/SM

__device__ __forceinline__ uint32_t smem_to_u32(const void* p) {
    uint32_t a;
    asm("{ .reg .u64 t; cvta.to.shared.u64 t, %1; cvt.u32.u64 %0, t; }" : "=r"(a) : "l"(p));
    return a;
}

__device__ __forceinline__ uint32_t f2h2(float a, float b) {
    __half2 h = __floats2half2_rn(a, b);
    return *reinterpret_cast<uint32_t*>(&h);
}

__device__ __forceinline__ void ldsm_x4(uint32_t addr, uint32_t& r0, uint32_t& r1,
                                        uint32_t& r2, uint32_t& r3) {
    asm volatile("ldmatrix.sync.aligned.m8n8.x4.shared.b16 {%0,%1,%2,%3}, [%4];"
                 : "=r"(r0), "=r"(r1), "=r"(r2), "=r"(r3) : "r"(addr));
}

__device__ __forceinline__ void mma_16816(float& d0, float& d1, float& d2, float& d3,
                                          uint32_t a0, uint32_t a1, uint32_t a2, uint32_t a3,
                                          uint32_t b0, uint32_t b1) {
    asm volatile(
        "mma.sync.aligned.m16n8k16.row.col.f32.f16.f16.f32 "
        "{%0,%1,%2,%3}, {%4,%5,%6,%7}, {%8,%9}, {%0,%1,%2,%3};"
        : "+f"(d0), "+f"(d1), "+f"(d2), "+f"(d3)
        : "r"(a0), "r"(a1), "r"(a2), "r"(a3), "r"(b0), "r"(b1));
}

#define CP_ASYNC16(dst, src) \
    asm volatile("cp.async.cg.shared.global [%0], [%1], 16;" :: "r"(dst), "l"(src) : "memory")
#define CP_COMMIT()  asm volatile("cp.async.commit_group;" ::: "memory")
#define CP_WAIT0()   asm volatile("cp.async.wait_group 0;" ::: "memory")
#define CP_WAIT1()   asm volatile("cp.async.wait_group 1;" ::: "memory")

// ============================================================================
// Kernel 1: convert clusters fp32 -> fp16 scratch, compute c2[K]. One warp/row.
// ============================================================================
__global__ void convert_clusters_kernel(const float* __restrict__ C) {
    const int row  = blockIdx.x * 8 + (threadIdx.x >> 5);
    const int lane = threadIdx.x & 31;
    const float4* src = reinterpret_cast<const float4*>(C + (size_t)row * D_DIM) + lane * 4;
    __half2* dst = reinterpret_cast<__half2*>(Ch_g + (size_t)row * D_DIM) + lane * 8;
    float sq = 0.f;
#pragma unroll
    for (int j = 0; j < 4; j++) {
        float4 v = src[j];
        sq = fmaf(v.x, v.x, sq); sq = fmaf(v.y, v.y, sq);
        sq = fmaf(v.z, v.z, sq); sq = fmaf(v.w, v.w, sq);
        dst[j * 2]     = __floats2half2_rn(v.x, v.y);
        dst[j * 2 + 1] = __floats2half2_rn(v.z, v.w);
    }
#pragma unroll
    for (int s = 16; s > 0; s >>= 1) sq += __shfl_xor_sync(0xFFFFFFFFu, sq, s);
    if (lane == 0) c2_g[row] = sq;
}

// ============================================================================
// Kernel 2: 8-warp HMMA GEMM, warp tile 64x64, fragment-double-buffered
// k-steps (LDSM of ks+1 issued before HMMA block of ks), 3-stage smem
// pipeline with one barrier per K-chunk. Fused distance/softassign epilogue.
// ============================================================================
__global__ void __launch_bounds__(THREADS, 1)
ClusteringLayer_88940182766172_kernel(const float* __restrict__ X,
                                      float* __restrict__ Out) {
    extern __shared__ char smem[];
    const uint32_t sb = smem_to_u32(smem);
    const int tid  = threadIdx.x;
    const int wid  = tid >> 5;
    const int lane = tid & 31;
    const int wm   = wid & 1;       // warp row  (2)
    const int wn   = wid >> 1;      // warp col  (4)
    const int row0 = blockIdx.x * TILE_M;

    float* x2s  = reinterpret_cast<float*>(smem + SM_X2);
    float* c2s  = reinterpret_cast<float*>(smem + SM_C2);
    float* sums = reinterpret_cast<float*>(smem + SM_SUMS);
    float* invs = reinterpret_cast<float*>(smem + SM_INV);

    // stage c2 into smem
    c2s[tid] = c2_g[tid];

    // ---- loader mappings ----
    // A: 2 threads per row; thread = (row tid>>1, half tid&1), 32 floats each.
    const float* Ap = X + (size_t)(row0 + (tid >> 1)) * D_DIM + (tid & 1) * 32;
    // B: 1 thread per cluster row; 64 fp16 (8 x 16B cp.async) per chunk.
    const __half* Bp = Ch_g + (size_t)tid * D_DIM;

    const uint32_t a_sts_base = (uint32_t)(tid >> 1) * 128 + (uint32_t)(tid & 1) * 64;
    const uint32_t b_sts_base = (uint32_t)tid * 128;

    // ---- ldmatrix addressing: swizzle reduced to per-thread constants ----
    // addr = StageBase + (band + tile*16 + rsel)*128 + ((ks*32 + csel) ^ sxor)
    const uint32_t rsel = (uint32_t)(lane & 15);
    const uint32_t csel = (uint32_t)(lane >> 4) * 16;
    const uint32_t sxor = (rsel & 7) << 4;
    const uint32_t arow = ((uint32_t)(wm * 64) + rsel) * 128;   // + mf*2048
    const uint32_t brow = ((uint32_t)(wn * 64) + rsel) * 128;   // + p*2048

    float4 av[8];
    float  x2a = 0.f;

    float acc[4][8][4];
#pragma unroll
    for (int a = 0; a < 4; a++)
#pragma unroll
        for (int b = 0; b < 8; b++)
#pragma unroll
            for (int c = 0; c < 4; c++) acc[a][b][c] = 0.f;

    // fragment double buffers
    uint32_t ar[2][4][4];
    uint32_t b0r[2][8], b1r[2][8];

#define LDG_A(i) do { \
        const float4* p_ = reinterpret_cast<const float4*>(Ap + (i) * CHUNK); \
        _Pragma("unroll") \
        for (int u_ = 0; u_ < 8; u_++) av[u_] = p_[u_]; \
        _Pragma("unroll") \
        for (int u_ = 0; u_ < 8; u_++) { \
            x2a = fmaf(av[u_].x, av[u_].x, x2a); x2a = fmaf(av[u_].y, av[u_].y, x2a); \
            x2a = fmaf(av[u_].z, av[u_].z, x2a); x2a = fmaf(av[u_].w, av[u_].w, x2a); \
        } \
    } while (0)

#define STS_A(stage) do { \
        char* base_ = smem + SM_A_BASE + (stage) * SM_A_STRIDE; \
        _Pragma("unroll") \
        for (int g_ = 0; g_ < 4; g_++) { \
            uint4 w_; \
            w_.x = f2h2(av[2*g_].x,   av[2*g_].y); \
            w_.y = f2h2(av[2*g_].z,   av[2*g_].w); \
            w_.z = f2h2(av[2*g_+1].x, av[2*g_+1].y); \
            w_.w = f2h2(av[2*g_+1].z, av[2*g_+1].w); \
            *reinterpret_cast<uint4*>(base_ + SW(a_sts_base + g_ * 16)) = w_; \
        } \
    } while (0)

#define CP_B(i, stage) do { \
        uint32_t dbase_ = sb + SM_B_BASE + (stage) * SM_B_STRIDE; \
        const __half* s_ = Bp + (i) * CHUNK; \
        _Pragma("unroll") \
        for (int u_ = 0; u_ < 8; u_++) \
            CP_ASYNC16(dbase_ + SW(b_sts_base + u_ * 16), s_ + u_ * 8); \
        CP_COMMIT(); \
    } while (0)

// Load all fragments for k-step `ks` from stage bases into set `st`.
#define LOAD_FRAGS(ks, st) do { \
        const uint32_t kc_ = (((uint32_t)(ks) * 32) + csel) ^ sxor; \
        _Pragma("unroll") \
        for (int mf_ = 0; mf_ < 4; mf_++) \
            ldsm_x4(Abase + arow + mf_ * 2048 + kc_, \
                    ar[st][mf_][0], ar[st][mf_][1], ar[st][mf_][2], ar[st][mf_][3]); \
        _Pragma("unroll") \
        for (int p_ = 0; p_ < 4; p_++) { \
            uint32_t r0_, r1_, r2_, r3_; \
            ldsm_x4(Bbase + brow + p_ * 2048 + kc_, r0_, r1_, r2_, r3_); \
            b0r[st][2*p_] = r0_; b0r[st][2*p_+1] = r1_; \
            b1r[st][2*p_] = r2_; b1r[st][2*p_+1] = r3_; \
        } \
    } while (0)

#define HMMA_BLOCK(st) do { \
        _Pragma("unroll") \
        for (int mf_ = 0; mf_ < 4; mf_++) \
            _Pragma("unroll") \
            for (int nf_ = 0; nf_ < 8; nf_++) \
                mma_16816(acc[mf_][nf_][0], acc[mf_][nf_][1], acc[mf_][nf_][2], acc[mf_][nf_][3], \
                          ar[st][mf_][0], ar[st][mf_][1], ar[st][mf_][2], ar[st][mf_][3], \
                          b0r[st][nf_], b1r[st][nf_]); \
    } while (0)

    // ---- prologue: fill stages 0 and 1 ----
    LDG_A(0); STS_A(0); CP_B(0, 0);
    LDG_A(1); STS_A(1); CP_B(1, 1);

    // ---- main loop over D chunks: ONE barrier per iteration ----
#pragma unroll 1
    for (int i = 0; i < NCHUNK; i++) {
        const int s = i % 3;

        if (i + 1 < NCHUNK) { CP_WAIT1(); } else { CP_WAIT0(); }
        __syncthreads();

        // next-next chunk producers (target stage (i+2)%3 == (i-1)%3, retired)
        if (i + 2 < NCHUNK) {
            LDG_A(i + 2);
            CP_B(i + 2, (i + 2) % 3);
        }

        const uint32_t Abase = sb + SM_A_BASE + s * SM_A_STRIDE;
        const uint32_t Bbase = sb + SM_B_BASE + s * SM_B_STRIDE;

        // k-step software pipeline: LDSM(ks+1) issued before HMMA(ks)
        LOAD_FRAGS(0, 0);
        LOAD_FRAGS(1, 1);
        HMMA_BLOCK(0);
        LOAD_FRAGS(2, 0);
        HMMA_BLOCK(1);
        LOAD_FRAGS(3, 1);
        HMMA_BLOCK(0);
        HMMA_BLOCK(1);

        if (i + 2 < NCHUNK) STS_A((i + 2) % 3);
    }

    // ---- x2 reduction (2 threads per row) ----
    {
        float s = x2a + __shfl_xor_sync(0xFFFFFFFFu, x2a, 1);
        if (!(tid & 1)) x2s[tid >> 1] = s;
    }
    __syncthreads();

    // ---- epilogue: q = 1/(1+dist), row sums, normalize, store ----
    float c2r[8][2];
#pragma unroll
    for (int nf = 0; nf < 8; nf++) {
#pragma unroll
        for (int e = 0; e < 2; e++)
            c2r[nf][e] = c2s[wn * 64 + nf * 8 + 2 * (lane & 3) + e];
    }

    float rsum[4][2];
#pragma unroll
    for (int mf = 0; mf < 4; mf++) {
#pragma unroll
        for (int h = 0; h < 2; h++) {
            const float x2v = x2s[wm * 64 + mf * 16 + h * 8 + (lane >> 2)];
            float s = 0.f;
#pragma unroll
            for (int nf = 0; nf < 8; nf++) {
#pragma unroll
                for (int e = 0; e < 2; e++) {
                    float xc = acc[mf][nf][2 * h + e];
                    float d  = fmaxf(x2v + c2r[nf][e] - 2.0f * xc, 0.0f);
                    float q  = __fdividef(1.0f, 1.0f + d);
                    acc[mf][nf][2 * h + e] = q;
                    s += q;
                }
            }
            rsum[mf][h] = s;
        }
    }
#pragma unroll
    for (int mf = 0; mf < 4; mf++)
#pragma unroll
        for (int h = 0; h < 2; h++) {
            float s = rsum[mf][h];
            s += __shfl_xor_sync(0xFFFFFFFFu, s, 1);
            s += __shfl_xor_sync(0xFFFFFFFFu, s, 2);
            if ((lane & 3) == 0)
                sums[(wm * 64 + mf * 16 + h * 8 + (lane >> 2)) * 4 + wn] = s;
        }
    __syncthreads();

    if (tid < 128)
        invs[tid] = __fdividef(1.0f, sums[tid * 4] + sums[tid * 4 + 1]
                                   + sums[tid * 4 + 2] + sums[tid * 4 + 3]);
    __syncthreads();

#pragma unroll
    for (int mf = 0; mf < 4; mf++) {
#pragma unroll
        for (int h = 0; h < 2; h++) {
            const int rloc = wm * 64 + mf * 16 + h * 8 + (lane >> 2);
            const float iv = invs[rloc];
            float* orow = Out + (size_t)(row0 + rloc) * K_CL + wn * 64 + 2 * (lane & 3);
#pragma unroll
            for (int nf = 0; nf < 8; nf++) {
                float2 v;
                v.x = acc[mf][nf][2 * h]     * iv;
                v.y = acc[mf][nf][2 * h + 1] * iv;
                *reinterpret_cast<float2*>(orow + nf * 8) = v;
            }
        }
    }
}

// ============================================================================
// Launch
// ============================================================================
extern "C" void kernel_launch(void* const* d_in, const int* in_sizes, int n_in,
                              void* d_out, int out_size) {
    const float* X = (const float*)d_in[0];
    const float* C = (const float*)d_in[1];
    if (n_in >= 2 && in_sizes[0] == K_CL * D_DIM && in_sizes[1] == N_ROWS * D_DIM) {
        const float* t = X; X = C; C = t;
    }
    float* Out = (float*)d_out;

    convert_clusters_kernel<<<K_CL / 8, 256>>>(C);

    cudaFuncSetAttribute(ClusteringLayer_88940182766172_kernel,
                         cudaFuncAttributeMaxDynamicSharedMemorySize, SMEM_TOTAL);
    ClusteringLayer_88940182766172_kernel<<<N_ROWS / TILE_M, THREADS, SMEM_TOTAL>>>(X, Out);
}

// round 11
// speedup vs baseline: 1.4138x; 1.4138x over previous
#include <cuda_runtime.h>
#include <cuda_fp16.h>
#include <cstdint>

// ============================================================================
// Problem constants
// ============================================================================
#define N_ROWS   65536
#define K_CL     256
#define D_DIM    512
#define TILE_M   128
#define CHUNK    64
#define NCHUNK   (D_DIM / CHUNK)   // 8
#define THREADS  512               // 16 warps: warp tile 64x32 (2M x 8N grid)

// fp16 copy of clusters + cluster squared norms (device scratch: allowed)
__device__ __half Ch_g[K_CL * D_DIM];
__device__ float  c2_g[K_CL];

// 128B-row XOR swizzle: 16B unit index ^= (row & 7). Conflict-free for
// ldmatrix / STS.128 / cp.async over 8-row groups with 128B row stride.
#define SW(off) ((off) ^ (((off) >> 3) & 0x70))

// Shared memory layout (bytes) — identical to the 116.9us R5 kernel.
#define SM_A0    0
#define SM_A1    16384
#define SM_B0    32768
#define SM_B1    65536
#define SM_X2    98304          // 128 f32
#define SM_C2    98816          // 256 f32
#define SM_SUMS  99840          // 128 x 8 f32 = 4096 B
#define SM_INV   103936         // 128 f32
#define SMEM_TOTAL 104448

__device__ __forceinline__ uint32_t smem_to_u32(const void* p) {
    uint32_t a;
    asm("{ .reg .u64 t; cvta.to.shared.u64 t, %1; cvt.u32.u64 %0, t; }" : "=r"(a) : "l"(p));
    return a;
}

__device__ __forceinline__ uint32_t f2h2(float a, float b) {
    __half2 h = __floats2half2_rn(a, b);
    return *reinterpret_cast<uint32_t*>(&h);
}

__device__ __forceinline__ void ldsm_x4(uint32_t addr, uint32_t& r0, uint32_t& r1,
                                        uint32_t& r2, uint32_t& r3) {
    asm volatile("ldmatrix.sync.aligned.m8n8.x4.shared.b16 {%0,%1,%2,%3}, [%4];"
                 : "=r"(r0), "=r"(r1), "=r"(r2), "=r"(r3) : "r"(addr));
}

__device__ __forceinline__ void mma_16816(float& d0, float& d1, float& d2, float& d3,
                                          uint32_t a0, uint32_t a1, uint32_t a2, uint32_t a3,
                                          uint32_t b0, uint32_t b1) {
    asm volatile(
        "mma.sync.aligned.m16n8k16.row.col.f32.f16.f16.f32 "
        "{%0,%1,%2,%3}, {%4,%5,%6,%7}, {%8,%9}, {%0,%1,%2,%3};"
        : "+f"(d0), "+f"(d1), "+f"(d2), "+f"(d3)
        : "r"(a0), "r"(a1), "r"(a2), "r"(a3), "r"(b0), "r"(b1));
}

#define CP_ASYNC16(dst, src) \
    asm volatile("cp.async.cg.shared.global [%0], [%1], 16;" :: "r"(dst), "l"(src) : "memory")
#define CP_COMMIT()  asm volatile("cp.async.commit_group;" ::: "memory")
#define CP_WAIT0()   asm volatile("cp.async.wait_group 0;" ::: "memory")

// ============================================================================
// Kernel 1: convert clusters fp32 -> fp16 scratch, compute c2[K]. One warp/row.
// ============================================================================
__global__ void convert_clusters_kernel(const float* __restrict__ C) {
    const int row  = blockIdx.x * 8 + (threadIdx.x >> 5);
    const int lane = threadIdx.x & 31;
    const float4* src = reinterpret_cast<const float4*>(C + (size_t)row * D_DIM) + lane * 4;
    __half2* dst = reinterpret_cast<__half2*>(Ch_g + (size_t)row * D_DIM) + lane * 8;
    float sq = 0.f;
#pragma unroll
    for (int j = 0; j < 4; j++) {
        float4 v = src[j];
        sq = fmaf(v.x, v.x, sq); sq = fmaf(v.y, v.y, sq);
        sq = fmaf(v.z, v.z, sq); sq = fmaf(v.w, v.w, sq);
        dst[j * 2]     = __floats2half2_rn(v.x, v.y);
        dst[j * 2 + 1] = __floats2half2_rn(v.z, v.w);
    }
#pragma unroll
    for (int s = 16; s > 0; s >>= 1) sq += __shfl_xor_sync(0xFFFFFFFFu, sq, s);
    if (lane == 0) c2_g[row] = sq;
}

// ============================================================================
// Kernel 2: tiled fp16 HMMA GEMM + fused distance/softassign epilogue.
// Exact R5 structure (116.9us best) + cross-warp k-step phase staggering:
// the 4 warps co-resident on each SMSP (wid>>2 distinct) start their k-step
// sequence at 4 different offsets, so LDSM bursts of some warps overlap HMMA
// bursts of others instead of convoying.
// ============================================================================
__global__ void __launch_bounds__(THREADS, 1)
ClusteringLayer_88940182766172_kernel(const float* __restrict__ X,
                                      float* __restrict__ Out) {
    extern __shared__ char smem[];
    const uint32_t sb = smem_to_u32(smem);
    const int tid  = threadIdx.x;
    const int wid  = tid >> 5;
    const int lane = tid & 31;
    const int wm   = wid & 1;       // warp row  (2)
    const int wn   = wid >> 1;      // warp col  (8)
    const int row0 = blockIdx.x * TILE_M;

    float* x2s  = reinterpret_cast<float*>(smem + SM_X2);
    float* c2s  = reinterpret_cast<float*>(smem + SM_C2);
    float* sums = reinterpret_cast<float*>(smem + SM_SUMS);
    float* invs = reinterpret_cast<float*>(smem + SM_INV);

    // stage c2 into smem
    if (tid < K_CL) c2s[tid] = c2_g[tid];

    // ---- loader mappings ----
    // A: 4 threads per row; thread = (row tid>>2, quarter tid&3), 16 floats each.
    const float* Ap = X + (size_t)(row0 + (tid >> 2)) * D_DIM + (tid & 3) * 16;
    // B: 2 threads per cluster row; thread = (row tid>>1, half tid&1), 32 fp16 each.
    const __half* Bp = Ch_g + (size_t)(tid >> 1) * D_DIM + (tid & 1) * 32;

    const uint32_t a_sts_base = (uint32_t)(tid >> 2) * 128 + (uint32_t)(tid & 3) * 32;
    const uint32_t b_sts_base = (uint32_t)(tid >> 1) * 128 + (uint32_t)(tid & 1) * 64;

    // ---- ldmatrix addressing: swizzle reduced to per-thread constants ----
    // full-offset XOR swizzle only depends on row bits (rsel&7) since the
    // k/csel part stays below bit 7: SW(off) == off ^ ((rsel&7)<<4).
    const uint32_t rsel = (uint32_t)(lane & 15);
    const uint32_t csel = (uint32_t)(lane >> 4) * 16;
    const uint32_t sxor = (rsel & 7) << 4;
    const uint32_t arow = ((uint32_t)(wm * 64) + rsel) * 128;   // + mf*2048
    const uint32_t brow = ((uint32_t)(wn * 32) + rsel) * 128;   // + p*2048
    const int      kphase = (wid >> 2) & 3;   // distinct among the 4 warps of one SMSP

    float4 av[4];
    float  x2a = 0.f;

    float acc[4][4][4];
#pragma unroll
    for (int a = 0; a < 4; a++)
#pragma unroll
        for (int b = 0; b < 4; b++)
#pragma unroll
            for (int c = 0; c < 4; c++) acc[a][b][c] = 0.f;

#define LDG_A(i) do { \
        const float4* p_ = reinterpret_cast<const float4*>(Ap + (i) * CHUNK); \
        _Pragma("unroll") \
        for (int u_ = 0; u_ < 4; u_++) av[u_] = p_[u_]; \
        _Pragma("unroll") \
        for (int u_ = 0; u_ < 4; u_++) { \
            x2a = fmaf(av[u_].x, av[u_].x, x2a); x2a = fmaf(av[u_].y, av[u_].y, x2a); \
            x2a = fmaf(av[u_].z, av[u_].z, x2a); x2a = fmaf(av[u_].w, av[u_].w, x2a); \
        } \
    } while (0)

#define STS_A(buf) do { \
        char* base_ = smem + ((buf) ? SM_A1 : SM_A0); \
        _Pragma("unroll") \
        for (int g_ = 0; g_ < 2; g_++) { \
            uint4 w_; \
            w_.x = f2h2(av[2*g_].x,   av[2*g_].y); \
            w_.y = f2h2(av[2*g_].z,   av[2*g_].w); \
            w_.z = f2h2(av[2*g_+1].x, av[2*g_+1].y); \
            w_.w = f2h2(av[2*g_+1].z, av[2*g_+1].w); \
            *reinterpret_cast<uint4*>(base_ + SW(a_sts_base + g_ * 16)) = w_; \
        } \
    } while (0)

#define CP_B(i, buf) do { \
        uint32_t dbase_ = sb + ((buf) ? SM_B1 : SM_B0); \
        const __half* s_ = Bp + (i) * CHUNK; \
        _Pragma("unroll") \
        for (int u_ = 0; u_ < 4; u_++) \
            CP_ASYNC16(dbase_ + SW(b_sts_base + u_ * 16), s_ + u_ * 8); \
        CP_COMMIT(); \
    } while (0)

    // ---- prologue: fill buffer 0 ----
    LDG_A(0);
    CP_B(0, 0);
    STS_A(0);
    CP_WAIT0();
    __syncthreads();

    // ---- main loop over D chunks ----
#pragma unroll 1
    for (int i = 0; i < NCHUNK; i++) {
        const int buf = i & 1;
        if (i < NCHUNK - 1) {
            LDG_A(i + 1);
            CP_B(i + 1, buf ^ 1);
        }

        const uint32_t Abase = sb + (buf ? SM_A1 : SM_A0);
        const uint32_t Bbase = sb + (buf ? SM_B1 : SM_B0);

#pragma unroll
        for (int kk = 0; kk < 4; kk++) {
            const int ks = (kk + kphase) & 3;         // staggered k-step order
            const uint32_t kc = (((uint32_t)ks * 32) + csel) ^ sxor;

            uint32_t ar[4][4];
#pragma unroll
            for (int mf = 0; mf < 4; mf++)
                ldsm_x4(Abase + arow + (uint32_t)mf * 2048 + kc,
                        ar[mf][0], ar[mf][1], ar[mf][2], ar[mf][3]);
            uint32_t b0r[4], b1r[4];
#pragma unroll
            for (int p = 0; p < 2; p++) {
                uint32_t r0, r1, r2, r3;
                ldsm_x4(Bbase + brow + (uint32_t)p * 2048 + kc, r0, r1, r2, r3);
                b0r[2*p] = r0; b0r[2*p+1] = r1; b1r[2*p] = r2; b1r[2*p+1] = r3;
            }
#pragma unroll
            for (int mf = 0; mf < 4; mf++)
#pragma unroll
                for (int nf = 0; nf < 4; nf++)
                    mma_16816(acc[mf][nf][0], acc[mf][nf][1], acc[mf][nf][2], acc[mf][nf][3],
                              ar[mf][0], ar[mf][1], ar[mf][2], ar[mf][3],
                              b0r[nf], b1r[nf]);
        }

        if (i < NCHUNK - 1) {
            __syncthreads();          // all warps done reading buf^1 (from iter i-1)
            STS_A(buf ^ 1);
            CP_WAIT0();
            __syncthreads();
        }
    }

    // ---- x2 reduction (4 threads per row; lanes differ in bits 0,1) ----
    {
        float s = x2a;
        s += __shfl_xor_sync(0xFFFFFFFFu, s, 1);
        s += __shfl_xor_sync(0xFFFFFFFFu, s, 2);
        if (!(tid & 3)) x2s[tid >> 2] = s;
    }
    __syncthreads();

    // ---- epilogue: q = 1/(1+dist), row sums, normalize, store ----
    float c2r[4][2];
#pragma unroll
    for (int nf = 0; nf < 4; nf++) {
#pragma unroll
        for (int e = 0; e < 2; e++)
            c2r[nf][e] = c2s[wn * 32 + nf * 8 + 2 * (lane & 3) + e];
    }

    float rsum[4][2];
#pragma unroll
    for (int mf = 0; mf < 4; mf++) {
#pragma unroll
        for (int h = 0; h < 2; h++) {
            const float x2v = x2s[wm * 64 + mf * 16 + h * 8 + (lane >> 2)];
            float s = 0.f;
#pragma unroll
            for (int nf = 0; nf < 4; nf++) {
#pragma unroll
                for (int e = 0; e < 2; e++) {
                    float xc = acc[mf][nf][2 * h + e];
                    float d  = fmaxf(x2v + c2r[nf][e] - 2.0f * xc, 0.0f);
                    float q  = __fdividef(1.0f, 1.0f + d);
                    acc[mf][nf][2 * h + e] = q;
                    s += q;
                }
            }
            rsum[mf][h] = s;
        }
    }
    // reduce across the 4 lanes sharing each row (lane>>2 constant)
#pragma unroll
    for (int mf = 0; mf < 4; mf++)
#pragma unroll
        for (int h = 0; h < 2; h++) {
            float s = rsum[mf][h];
            s += __shfl_xor_sync(0xFFFFFFFFu, s, 1);
            s += __shfl_xor_sync(0xFFFFFFFFu, s, 2);
            if ((lane & 3) == 0)
                sums[(wm * 64 + mf * 16 + h * 8 + (lane >> 2)) * 8 + wn] = s;
        }
    __syncthreads();

    if (tid < 128) {
        float t = 0.f;
#pragma unroll
        for (int j = 0; j < 8; j++) t += sums[tid * 8 + j];
        invs[tid] = __fdividef(1.0f, t);
    }
    __syncthreads();

#pragma unroll
    for (int mf = 0; mf < 4; mf++) {
#pragma unroll
        for (int h = 0; h < 2; h++) {
            const int rloc = wm * 64 + mf * 16 + h * 8 + (lane >> 2);
            const float iv = invs[rloc];
            float* orow = Out + (size_t)(row0 + rloc) * K_CL + wn * 32 + 2 * (lane & 3);
#pragma unroll
            for (int nf = 0; nf < 4; nf++) {
                float2 v;
                v.x = acc[mf][nf][2 * h]     * iv;
                v.y = acc[mf][nf][2 * h + 1] * iv;
                *reinterpret_cast<float2*>(orow + nf * 8) = v;
            }
        }
    }
}

// ============================================================================
// Launch
// ============================================================================
extern "C" void kernel_launch(void* const* d_in, const int* in_sizes, int n_in,
                              void* d_out, int out_size) {
    const float* X = (const float*)d_in[0];
    const float* C = (const float*)d_in[1];
    if (n_in >= 2 && in_sizes[0] == K_CL * D_DIM && in_sizes[1] == N_ROWS * D_DIM) {
        const float* t = X; X = C; C = t;
    }
    float* Out = (float*)d_out;

    convert_clusters_kernel<<<K_CL / 8, 256>>>(C);

    cudaFuncSetAttribute(ClusteringLayer_88940182766172_kernel,
                         cudaFuncAttributeMaxDynamicSharedMemorySize, SMEM_TOTAL);
    ClusteringLayer_88940182766172_kernel<<<N_ROWS / TILE_M, THREADS, SMEM_TOTAL>>>(X, Out);
}

// round 12
// speedup vs baseline: 1.4829x; 1.0489x over previous
#include <cuda_runtime.h>
#include <cuda_fp16.h>
#include <cstdint>

// ============================================================================
// Problem constants
// ============================================================================
#define N_ROWS   65536
#define K_CL     256
#define D_DIM    512
#define TILE_M   128
#define CHUNK    64
#define NCHUNK   (D_DIM / CHUNK)   // 8
#define THREADS  512               // 16 warps: warp tile 64x32 (2M x 8N grid)

// fp16 copy of clusters + cluster squared norms (device scratch: allowed)
__device__ __half Ch_g[K_CL * D_DIM];
__device__ float  c2_g[K_CL];

// 128B-row XOR swizzle: 16B unit index ^= (row & 7).
#define SW(off) ((off) ^ (((off) >> 3) & 0x70))

// Shared memory layout (bytes) — identical to the R5/R11 kernels.
#define SM_A0    0
#define SM_A1    16384
#define SM_B0    32768
#define SM_B1    65536
#define SM_X2    98304          // 128 f32
#define SM_C2    98816          // 256 f32
#define SM_SUMS  99840          // 128 x 8 f32 = 4096 B
#define SM_INV   103936         // 128 f32
#define SMEM_TOTAL 104448

__device__ __forceinline__ uint32_t smem_to_u32(const void* p) {
    uint32_t a;
    asm("{ .reg .u64 t; cvta.to.shared.u64 t, %1; cvt.u32.u64 %0, t; }" : "=r"(a) : "l"(p));
    return a;
}

__device__ __forceinline__ uint32_t f2h2(float a, float b) {
    __half2 h = __floats2half2_rn(a, b);
    return *reinterpret_cast<uint32_t*>(&h);
}

__device__ __forceinline__ void ldsm_x4(uint32_t addr, uint32_t& r0, uint32_t& r1,
                                        uint32_t& r2, uint32_t& r3) {
    asm volatile("ldmatrix.sync.aligned.m8n8.x4.shared.b16 {%0,%1,%2,%3}, [%4];"
                 : "=r"(r0), "=r"(r1), "=r"(r2), "=r"(r3) : "r"(addr));
}

__device__ __forceinline__ void mma_16816(float& d0, float& d1, float& d2, float& d3,
                                          uint32_t a0, uint32_t a1, uint32_t a2, uint32_t a3,
                                          uint32_t b0, uint32_t b1) {
    asm volatile(
        "mma.sync.aligned.m16n8k16.row.col.f32.f16.f16.f32 "
        "{%0,%1,%2,%3}, {%4,%5,%6,%7}, {%8,%9}, {%0,%1,%2,%3};"
        : "+f"(d0), "+f"(d1), "+f"(d2), "+f"(d3)
        : "r"(a0), "r"(a1), "r"(a2), "r"(a3), "r"(b0), "r"(b1));
}

#define CP_ASYNC16(dst, src) \
    asm volatile("cp.async.cg.shared.global [%0], [%1], 16;" :: "r"(dst), "l"(src) : "memory")
#define CP_COMMIT()  asm volatile("cp.async.commit_group;" ::: "memory")
#define CP_WAIT0()   asm volatile("cp.async.wait_group 0;" ::: "memory")

// ============================================================================
// Kernel 1: convert clusters fp32 -> fp16 scratch, compute c2[K]. One warp/row.
// ============================================================================
__global__ void convert_clusters_kernel(const float* __restrict__ C) {
    const int row  = blockIdx.x * 8 + (threadIdx.x >> 5);
    const int lane = threadIdx.x & 31;
    const float4* src = reinterpret_cast<const float4*>(C + (size_t)row * D_DIM) + lane * 4;
    __half2* dst = reinterpret_cast<__half2*>(Ch_g + (size_t)row * D_DIM) + lane * 8;
    float sq = 0.f;
#pragma unroll
    for (int j = 0; j < 4; j++) {
        float4 v = src[j];
        sq = fmaf(v.x, v.x, sq); sq = fmaf(v.y, v.y, sq);
        sq = fmaf(v.z, v.z, sq); sq = fmaf(v.w, v.w, sq);
        dst[j * 2]     = __floats2half2_rn(v.x, v.y);
        dst[j * 2 + 1] = __floats2half2_rn(v.z, v.w);
    }
#pragma unroll
    for (int s = 16; s > 0; s >>= 1) sq += __shfl_xor_sync(0xFFFFFFFFu, sq, s);
    if (lane == 0) c2_g[row] = sq;
}

// ============================================================================
// Kernel 2: tiled fp16 HMMA GEMM + fused distance/softassign epilogue.
// R11 tiling (16 warps, 64x32 warp tile, k-step stagger) with the mainloop
// rebuilt so NO instruction ever waits on an in-flight LDG:
//   iter i top:  CP_B(i+1) ; STS_A+x2(i+1)  [av loaded one full chunk ago]
//                LDG_A(i+2) [lands during THIS chunk's MMA]
//        body:  MMA(buf i&1)
//      bottom:  cp.wait + ONE barrier
// WAR safety: buf^1's readers all finished in iter i-1 (its end barrier).
// ============================================================================
__global__ void __launch_bounds__(THREADS, 1)
ClusteringLayer_88940182766172_kernel(const float* __restrict__ X,
                                      float* __restrict__ Out) {
    extern __shared__ char smem[];
    const uint32_t sb = smem_to_u32(smem);
    const int tid  = threadIdx.x;
    const int wid  = tid >> 5;
    const int lane = tid & 31;
    const int wm   = wid & 1;       // warp row  (2)
    const int wn   = wid >> 1;      // warp col  (8)
    const int row0 = blockIdx.x * TILE_M;

    float* x2s  = reinterpret_cast<float*>(smem + SM_X2);
    float* c2s  = reinterpret_cast<float*>(smem + SM_C2);
    float* sums = reinterpret_cast<float*>(smem + SM_SUMS);
    float* invs = reinterpret_cast<float*>(smem + SM_INV);

    if (tid < K_CL) c2s[tid] = c2_g[tid];

    // ---- loader mappings ----
    const float* Ap = X + (size_t)(row0 + (tid >> 2)) * D_DIM + (tid & 3) * 16;
    const __half* Bp = Ch_g + (size_t)(tid >> 1) * D_DIM + (tid & 1) * 32;

    const uint32_t a_sts_base = (uint32_t)(tid >> 2) * 128 + (uint32_t)(tid & 3) * 32;
    const uint32_t b_sts_base = (uint32_t)(tid >> 1) * 128 + (uint32_t)(tid & 1) * 64;

    // ---- ldmatrix addressing: per-warp constants, rotated k-step order ----
    const uint32_t rsel = (uint32_t)(lane & 15);
    const uint32_t csel = (uint32_t)(lane >> 4) * 16;
    const uint32_t sxor = (rsel & 7) << 4;
    const uint32_t arow = ((uint32_t)(wm * 64) + rsel) * 128;
    const uint32_t brow = ((uint32_t)(wn * 32) + rsel) * 128;
    const int      kphase = (wid >> 2) & 3;

    // precomputed, rotation baked in: zero per-k-step address ALU beyond 1 add
    uint32_t akc[4], bkc[4];
#pragma unroll
    for (int kk = 0; kk < 4; kk++) {
        const uint32_t ks = (uint32_t)((kk + kphase) & 3);
        const uint32_t kc = (ks * 32 + csel) ^ sxor;
        akc[kk] = arow + kc;
        bkc[kk] = brow + kc;
    }

    float4 av[4];
    float  x2a = 0.f;

    float acc[4][4][4];
#pragma unroll
    for (int a = 0; a < 4; a++)
#pragma unroll
        for (int b = 0; b < 4; b++)
#pragma unroll
            for (int c = 0; c < 4; c++) acc[a][b][c] = 0.f;

// pure load, no dependent math
#define LDG_A(i) do { \
        const float4* p_ = reinterpret_cast<const float4*>(Ap + (i) * CHUNK); \
        _Pragma("unroll") \
        for (int u_ = 0; u_ < 4; u_++) av[u_] = p_[u_]; \
    } while (0)

// convert + store + x2 accumulation (av was loaded a full chunk earlier)
#define STS_A_X2(buf) do { \
        char* base_ = smem + ((buf) ? SM_A1 : SM_A0); \
        _Pragma("unroll") \
        for (int u_ = 0; u_ < 4; u_++) { \
            x2a = fmaf(av[u_].x, av[u_].x, x2a); x2a = fmaf(av[u_].y, av[u_].y, x2a); \
            x2a = fmaf(av[u_].z, av[u_].z, x2a); x2a = fmaf(av[u_].w, av[u_].w, x2a); \
        } \
        _Pragma("unroll") \
        for (int g_ = 0; g_ < 2; g_++) { \
            uint4 w_; \
            w_.x = f2h2(av[2*g_].x,   av[2*g_].y); \
            w_.y = f2h2(av[2*g_].z,   av[2*g_].w); \
            w_.z = f2h2(av[2*g_+1].x, av[2*g_+1].y); \
            w_.w = f2h2(av[2*g_+1].z, av[2*g_+1].w); \
            *reinterpret_cast<uint4*>(base_ + SW(a_sts_base + g_ * 16)) = w_; \
        } \
    } while (0)

#define CP_B(i, buf) do { \
        uint32_t dbase_ = sb + ((buf) ? SM_B1 : SM_B0); \
        const __half* s_ = Bp + (i) * CHUNK; \
        _Pragma("unroll") \
        for (int u_ = 0; u_ < 4; u_++) \
            CP_ASYNC16(dbase_ + SW(b_sts_base + u_ * 16), s_ + u_ * 8); \
        CP_COMMIT(); \
    } while (0)

    // ---- prologue: chunk 0 staged; chunk 1's A pre-loaded into av ----
    LDG_A(0);
    STS_A_X2(0);
    CP_B(0, 0);
    LDG_A(1);
    CP_WAIT0();
    __syncthreads();

    // ---- main loop: ONE barrier per chunk, no exposed LDG dependency ----
#pragma unroll 1
    for (int i = 0; i < NCHUNK; i++) {
        const int buf = i & 1;

        if (i + 1 < NCHUNK) {
            CP_B(i + 1, buf ^ 1);      // WAR-safe: buf^1 readers done in iter i-1
            STS_A_X2(buf ^ 1);         // av = chunk i+1 (loaded one chunk ago)
            if (i + 2 < NCHUNK) LDG_A(i + 2);   // lands during this MMA block
        }

        const uint32_t Abase = sb + (buf ? SM_A1 : SM_A0);
        const uint32_t Bbase = sb + (buf ? SM_B1 : SM_B0);

#pragma unroll
        for (int kk = 0; kk < 4; kk++) {
            const uint32_t ab = Abase + akc[kk];
            const uint32_t bb = Bbase + bkc[kk];
            uint32_t ar[4][4];
#pragma unroll
            for (int mf = 0; mf < 4; mf++)
                ldsm_x4(ab + (uint32_t)mf * 2048,
                        ar[mf][0], ar[mf][1], ar[mf][2], ar[mf][3]);
            uint32_t b0r[4], b1r[4];
#pragma unroll
            for (int p = 0; p < 2; p++) {
                uint32_t r0, r1, r2, r3;
                ldsm_x4(bb + (uint32_t)p * 2048, r0, r1, r2, r3);
                b0r[2*p] = r0; b0r[2*p+1] = r1; b1r[2*p] = r2; b1r[2*p+1] = r3;
            }
#pragma unroll
            for (int mf = 0; mf < 4; mf++)
#pragma unroll
                for (int nf = 0; nf < 4; nf++)
                    mma_16816(acc[mf][nf][0], acc[mf][nf][1], acc[mf][nf][2], acc[mf][nf][3],
                              ar[mf][0], ar[mf][1], ar[mf][2], ar[mf][3],
                              b0r[nf], b1r[nf]);
        }

        if (i + 1 < NCHUNK) {
            CP_WAIT0();
            __syncthreads();
        }
    }

    // ---- x2 reduction (4 threads per row; lanes differ in bits 0,1) ----
    {
        float s = x2a;
        s += __shfl_xor_sync(0xFFFFFFFFu, s, 1);
        s += __shfl_xor_sync(0xFFFFFFFFu, s, 2);
        if (!(tid & 3)) x2s[tid >> 2] = s;
    }
    __syncthreads();

    // ---- epilogue: q = 1/(1+dist), row sums, normalize, store ----
    float c2r[4][2];
#pragma unroll
    for (int nf = 0; nf < 4; nf++) {
#pragma unroll
        for (int e = 0; e < 2; e++)
            c2r[nf][e] = c2s[wn * 32 + nf * 8 + 2 * (lane & 3) + e];
    }

    float rsum[4][2];
#pragma unroll
    for (int mf = 0; mf < 4; mf++) {
#pragma unroll
        for (int h = 0; h < 2; h++) {
            const float x2v = x2s[wm * 64 + mf * 16 + h * 8 + (lane >> 2)];
            float s = 0.f;
#pragma unroll
            for (int nf = 0; nf < 4; nf++) {
#pragma unroll
                for (int e = 0; e < 2; e++) {
                    float xc = acc[mf][nf][2 * h + e];
                    float d  = fmaxf(x2v + c2r[nf][e] - 2.0f * xc, 0.0f);
                    float q  = __fdividef(1.0f, 1.0f + d);
                    acc[mf][nf][2 * h + e] = q;
                    s += q;
                }
            }
            rsum[mf][h] = s;
        }
    }
#pragma unroll
    for (int mf = 0; mf < 4; mf++)
#pragma unroll
        for (int h = 0; h < 2; h++) {
            float s = rsum[mf][h];
            s += __shfl_xor_sync(0xFFFFFFFFu, s, 1);
            s += __shfl_xor_sync(0xFFFFFFFFu, s, 2);
            if ((lane & 3) == 0)
                sums[(wm * 64 + mf * 16 + h * 8 + (lane >> 2)) * 8 + wn] = s;
        }
    __syncthreads();

    if (tid < 128) {
        float t = 0.f;
#pragma unroll
        for (int j = 0; j < 8; j++) t += sums[tid * 8 + j];
        invs[tid] = __fdividef(1.0f, t);
    }
    __syncthreads();

#pragma unroll
    for (int mf = 0; mf < 4; mf++) {
#pragma unroll
        for (int h = 0; h < 2; h++) {
            const int rloc = wm * 64 + mf * 16 + h * 8 + (lane >> 2);
            const float iv = invs[rloc];
            float* orow = Out + (size_t)(row0 + rloc) * K_CL + wn * 32 + 2 * (lane & 3);
#pragma unroll
            for (int nf = 0; nf < 4; nf++) {
                float2 v;
                v.x = acc[mf][nf][2 * h]     * iv;
                v.y = acc[mf][nf][2 * h + 1] * iv;
                *reinterpret_cast<float2*>(orow + nf * 8) = v;
            }
        }
    }
}

// ============================================================================
// Launch
// ============================================================================
extern "C" void kernel_launch(void* const* d_in, const int* in_sizes, int n_in,
                              void* d_out, int out_size) {
    const float* X = (const float*)d_in[0];
    const float* C = (const float*)d_in[1];
    if (n_in >= 2 && in_sizes[0] == K_CL * D_DIM && in_sizes[1] == N_ROWS * D_DIM) {
        const float* t = X; X = C; C = t;
    }
    float* Out = (float*)d_out;

    convert_clusters_kernel<<<K_CL / 8, 256>>>(C);

    cudaFuncSetAttribute(ClusteringLayer_88940182766172_kernel,
                         cudaFuncAttributeMaxDynamicSharedMemorySize, SMEM_TOTAL);
    ClusteringLayer_88940182766172_kernel<<<N_ROWS / TILE_M, THREADS, SMEM_TOTAL>>>(X, Out);
}